// round 1
// baseline (speedup 1.0000x reference)
#include <cuda_runtime.h>
#include <math.h>

#define HW2 2304
#define HH 48
#define WW 48

// ---------------- device scratch (no allocations allowed) ----------------
__device__ float g_xenc  [2*64 *HW2];
__device__ float g_yenc  [2*64 *HW2];
__device__ float g_f512a [2*512*HW2];
__device__ float g_f512b [2*512*HW2];
__device__ float g_cols  [2*4608*HW2];   // 21.2M floats, reused for every im2col
__device__ float g_offb  [2*18 *HW2];
__device__ float g_f177  [2*177*HW2];
__device__ float g_f177b [2*177*HW2];
__device__ float g_wb1   [2*64*576];
__device__ float g_wb2   [2*64*144];
__device__ float g_wb3   [2*256*36];
__device__ float g_fwb   [2*256];
__device__ float g_adw   [2*256*HW2];    // per-batch adaptive weights (max 256x2304)
__device__ float g_def0  [2*256*HW2];
__device__ float g_def1  [2*256*HW2];
__device__ float g_s1o   [2*128*HW2];
__device__ float g_s2o   [2*64*HW2];
__device__ float g_swa   [2*HW2];
__device__ float g_swb   [2*HW2];

// ---------------- generic tiled fp32 GEMM: C[M,N] = A[M,K] * B[K,N] ----------------
// gridDim.z = batch; per-batch element strides sA/sB/sC (sA=0 => shared weights).
__global__ void gemm64(const float* __restrict__ A, const float* __restrict__ B,
                       float* __restrict__ C, int M, int N, int K,
                       long long sA, long long sB, long long sC,
                       const float* __restrict__ bias, int relu)
{
    A += (long long)blockIdx.z * sA;
    B += (long long)blockIdx.z * sB;
    C += (long long)blockIdx.z * sC;
    __shared__ float As[16][64];
    __shared__ float Bs[16][68];
    int tx = threadIdx.x, ty = threadIdx.y;
    int tid = ty * 16 + tx;
    int m0 = blockIdx.y * 64, n0 = blockIdx.x * 64;
    int mA = tid >> 2, kA = (tid & 3) * 4;
    int kB = tid >> 4, nB = (tid & 15) * 4;
    float acc[4][4];
#pragma unroll
    for (int i = 0; i < 4; i++)
#pragma unroll
        for (int j = 0; j < 4; j++) acc[i][j] = 0.f;

    for (int k0 = 0; k0 < K; k0 += 16) {
#pragma unroll
        for (int i = 0; i < 4; i++) {
            int k = k0 + kA + i;
            As[kA + i][mA] = (m0 + mA < M && k < K) ? A[(long long)(m0 + mA) * K + k] : 0.f;
        }
#pragma unroll
        for (int i = 0; i < 4; i++) {
            int n = n0 + nB + i;
            Bs[kB][nB + i] = (k0 + kB < K && n < N) ? B[(long long)(k0 + kB) * N + n] : 0.f;
        }
        __syncthreads();
#pragma unroll
        for (int kk = 0; kk < 16; kk++) {
            float a[4], b[4];
#pragma unroll
            for (int i = 0; i < 4; i++) a[i] = As[kk][ty * 4 + i];
#pragma unroll
            for (int j = 0; j < 4; j++) b[j] = Bs[kk][tx * 4 + j];
#pragma unroll
            for (int i = 0; i < 4; i++)
#pragma unroll
                for (int j = 0; j < 4; j++) acc[i][j] += a[i] * b[j];
        }
        __syncthreads();
    }
#pragma unroll
    for (int i = 0; i < 4; i++) {
        int m = m0 + ty * 4 + i;
        if (m >= M) continue;
        float bv = bias ? bias[m] : 0.f;
#pragma unroll
        for (int j = 0; j < 4; j++) {
            int n = n0 + tx * 4 + j;
            if (n >= N) continue;
            float v = acc[i][j] + bv;
            if (relu) v = fmaxf(v, 0.f);
            C[(long long)m * N + n] = v;
        }
    }
}

// ---------------- deformable (or plain) 3x3 s1 p1 im2col over 48x48 ----------------
// cols[b, c*9+q, hw] ; off: (B,18,HW) layout, channel 2q = dy, 2q+1 = dx; off==null => identity taps.
// grid: x = ceil(HW/256), y = b*9+q (18), z = c-chunk of 64
__global__ void deform_im2col_k(const float* __restrict__ src, long long srcB,
                                const float* __restrict__ off,
                                float* __restrict__ cols, int C)
{
    int hw = blockIdx.x * 256 + threadIdx.x;
    if (hw >= HW2) return;
    int bq = blockIdx.y;
    int b = bq / 9, q = bq % 9;
    int ki = q / 3, kj = q % 3;
    int h = hw / WW, w = hw % WW;
    const float* sb = src + (long long)b * srcB;
    float* cb = cols + (long long)b * C * 9 * HW2;
    int c0 = blockIdx.z * 64;
    int c1 = c0 + 64; if (c1 > C) c1 = C;

    if (off == nullptr) {
        int y = h - 1 + ki, x = w - 1 + kj;
        bool vin = (y >= 0 && y < HH && x >= 0 && x < WW);
        int idx = vin ? (y * WW + x) : 0;
        for (int c = c0; c < c1; c++) {
            float v = vin ? sb[(long long)c * HW2 + idx] : 0.f;
            cb[((long long)c * 9 + q) * HW2 + hw] = v;
        }
    } else {
        float py = (float)(h - 1 + ki) + off[((long long)b * 18 + 2 * q) * HW2 + hw];
        float px = (float)(w - 1 + kj) + off[((long long)b * 18 + 2 * q + 1) * HW2 + hw];
        float fy = floorf(py), fx = floorf(px);
        float ay = py - fy, ax = px - fx;
        int y0 = (int)fy, x0 = (int)fx;
        int y1 = y0 + 1, x1 = x0 + 1;
        bool by0 = (y0 >= 0 && y0 < HH), by1 = (y1 >= 0 && y1 < HH);
        bool bx0 = (x0 >= 0 && x0 < WW), bx1 = (x1 >= 0 && x1 < WW);
        int yc0 = min(max(y0, 0), HH - 1), yc1 = min(max(y1, 0), HH - 1);
        int xc0 = min(max(x0, 0), WW - 1), xc1 = min(max(x1, 0), WW - 1);
        float w00 = (by0 && bx0) ? (1.f - ay) * (1.f - ax) : 0.f;
        float w01 = (by0 && bx1) ? (1.f - ay) * ax : 0.f;
        float w10 = (by1 && bx0) ? ay * (1.f - ax) : 0.f;
        float w11 = (by1 && bx1) ? ay * ax : 0.f;
        int i00 = yc0 * WW + xc0, i01 = yc0 * WW + xc1;
        int i10 = yc1 * WW + xc0, i11 = yc1 * WW + xc1;
        for (int c = c0; c < c1; c++) {
            const float* s = sb + (long long)c * HW2;
            float v = w00 * s[i00] + w01 * s[i01] + w10 * s[i10] + w11 * s[i11];
            cb[((long long)c * 9 + q) * HW2 + hw] = v;
        }
    }
}

// ---------------- generic strided im2col (for 5x5 s2 p2 and 3x3 s2 p1) ----------------
// grid: x=ceil(OH*OW/256), y = row (c*KH*KW + kh*KW + kw), z = batch
__global__ void im2col_g(const float* __restrict__ src, long long srcB,
                         float* __restrict__ cols,
                         int C, int H, int W, int KH, int KW,
                         int stride, int pad, int OH, int OW)
{
    int ohw = blockIdx.x * 256 + threadIdx.x;
    int OHW = OH * OW;
    if (ohw >= OHW) return;
    int row = blockIdx.y;
    int b = blockIdx.z;
    int kk = row % (KH * KW);
    int c = row / (KH * KW);
    int kh = kk / KW, kw = kk % KW;
    int oh = ohw / OW, ow = ohw % OW;
    int ih = oh * stride - pad + kh;
    int iw = ow * stride - pad + kw;
    float v = 0.f;
    if (ih >= 0 && ih < H && iw >= 0 && iw < W)
        v = src[(long long)b * srcB + ((long long)c * H + ih) * W + iw];
    cols[((long long)b * C * KH * KW + row) * OHW + ohw] = v;
}

// ---------------- direct 3x3 s1 p1 conv on 48x48 (small O: 18-ch offset heads, s3) ----------------
__global__ void conv3x3_direct(const float* __restrict__ in, long long inB,
                               const float* __restrict__ w, float* __restrict__ out,
                               long long outB, int C, int relu)
{
    int hw = blockIdx.x * 256 + threadIdx.x;
    if (hw >= HW2) return;
    int o = blockIdx.y, b = blockIdx.z;
    int h = hw / WW, x = hw % WW;
    const float* ib = in + (long long)b * inB;
    const float* wo = w + (long long)o * C * 9;
    float acc = 0.f;
    for (int c = 0; c < C; c++) {
        const float* ic = ib + (long long)c * HW2;
        const float* wc = wo + c * 9;
#pragma unroll
        for (int kh = 0; kh < 3; kh++) {
            int ih = h + kh - 1;
            if (ih < 0 || ih >= HH) continue;
#pragma unroll
            for (int kw = 0; kw < 3; kw++) {
                int iw = x + kw - 1;
                if (iw < 0 || iw >= WW) continue;
                acc += ic[ih * WW + iw] * wc[kh * 3 + kw];
            }
        }
    }
    if (relu) acc = fmaxf(acc, 0.f);
    out[(long long)b * outB + (long long)o * HW2 + hw] = acc;
}

// ---------------- elementwise kernels ----------------
__global__ void concat_k(const float* __restrict__ a, const float* __restrict__ b_,
                         float* __restrict__ o, long long imgStride)
{
    int idx = blockIdx.x * 256 + threadIdx.x;
    if (idx >= 2 * 512 * HW2) return;
    int bb = idx / (512 * HW2);
    int c = (idx / HW2) % 512;
    int hw = idx % HW2;
    float v = (c < 256) ? a[bb * imgStride + (long long)c * HW2 + hw]
                        : b_[bb * imgStride + (long long)(c - 256) * HW2 + hw];
    o[idx] = v;
}

__global__ void corr_k(const float* __restrict__ Ra, const float* __restrict__ Tb,
                       float* __restrict__ f177)
{
    int idx = blockIdx.x * 256 + threadIdx.x;
    if (idx >= 2 * 49 * HW2) return;
    int b = idx / (49 * HW2);
    int q = (idx / HW2) % 49;
    int hw = idx % HW2;
    int h = hw / WW, w = hw % WW;
    int dy = 2 * ((q / 7) - 3), dx = 2 * ((q % 7) - 3);
    int hh = h + dy, ww = w + dx;
    float s = 0.f;
    if (hh >= 0 && hh < HH && ww >= 0 && ww < WW) {
        const float* a = Ra + (long long)b * (2 * 64 * HW2) + hw;
        const float* bp = Tb + (long long)b * (2 * 64 * HW2) + hh * WW + ww;
        for (int c = 0; c < 64; c++) s += a[c * HW2] * bp[c * HW2];
    }
    f177[((long long)b * 177 + q) * HW2 + hw] = s * (1.f / 64.f);
}

__global__ void pack_k(const float* __restrict__ eA, const float* __restrict__ eB,
                       float* __restrict__ f177)
{
    int idx = blockIdx.x * 256 + threadIdx.x;
    if (idx >= 2 * 64 * HW2) return;
    int b = idx / (64 * HW2);
    int c = (idx / HW2) % 64;
    int hw = idx % HW2;
    f177[((long long)b * 177 + 49 + c) * HW2 + hw] = eA[idx];
    f177[((long long)b * 177 + 113 + c) * HW2 + hw] = eB[idx];
}

__global__ void mean36_k(const float* __restrict__ in, float* __restrict__ fw, int total)
{
    int i = blockIdx.x * 256 + threadIdx.x;
    if (i >= total) return;
    float s = 0.f;
#pragma unroll
    for (int j = 0; j < 36; j++) s += in[i * 36 + j];
    fw[i] = s * (1.f / 36.f);
}

__global__ void mkw_k(const float* __restrict__ fw, const float* __restrict__ Wt,
                      const float* __restrict__ Bi, float* __restrict__ adw,
                      int M, int Kc, int total)
{
    int idx = blockIdx.x * 256 + threadIdx.x;
    if (idx >= total) return;
    int b = idx / (M * Kc);
    int r = idx - b * M * Kc;
    int o = r / Kc;
    adw[idx] = fw[b * M + o] * Wt[r] + Bi[r];
}

__global__ void final_k(const float* __restrict__ d0, const float* __restrict__ d1,
                        const float* __restrict__ s0p, const float* __restrict__ s1p,
                        float* __restrict__ out, int total)
{
    int idx = blockIdx.x * 256 + threadIdx.x;
    if (idx >= total) return;
    int b = idx / (256 * HW2);
    int hw = idx % HW2;
    float s0 = s0p[b * HW2 + hw];
    float s1 = s1p[b * HW2 + hw];
    const float eps = 1e-8f;
    float wx = (s0 * s1) / (fmaxf(fabsf(s0), eps) * fmaxf(fabsf(s1), eps));
    float wy = (s1 * s1) / (fmaxf(fabsf(s1), eps) * fmaxf(fabsf(s1), eps));
    float mx = fmaxf(wx, wy);
    float e0 = expf(wx - mx), e1 = expf(wy - mx);
    float inv = 1.f / (e0 + e1);
    out[idx] = d0[idx] * (e0 * inv) + d1[idx] * (e1 * inv);
}

// ---------------- host orchestration ----------------
extern "C" void kernel_launch(void* const* d_in, const int* in_sizes, int n_in,
                              void* d_out, int out_size)
{
    (void)in_sizes; (void)n_in; (void)out_size;
    const float* R0     = (const float*)d_in[0];
    const float* T0     = (const float*)d_in[1];
    const float* inp    = (const float*)d_in[2];
    const float* enc0_w = (const float*)d_in[3];
    const float* enc0_b = (const float*)d_in[4];
    const float* enc1_w = (const float*)d_in[5];
    const float* enc1_b = (const float*)d_in[6];
    const float* offw[4] = {(const float*)d_in[7], (const float*)d_in[8],
                            (const float*)d_in[9], (const float*)d_in[10]};
    const float* defw[3] = {(const float*)d_in[11], (const float*)d_in[12],
                            (const float*)d_in[13]};
    const float* w0a = (const float*)d_in[14];
    const float* w0b = (const float*)d_in[15];
    const float* w0c = (const float*)d_in[16];
    const float* w1a = (const float*)d_in[17];
    const float* w1b = (const float*)d_in[18];
    const float* w1c = (const float*)d_in[19];
    const float* wx_w  = (const float*)d_in[20];
    const float* wx_b  = (const float*)d_in[21];
    const float* wxf_w = (const float*)d_in[22];
    const float* wxf_b = (const float*)d_in[23];
    const float* s1w = (const float*)d_in[24];
    const float* s2w = (const float*)d_in[25];
    const float* s3w = (const float*)d_in[26];
    float* out = (float*)d_out;

    float *xenc, *yenc, *f512a, *f512b, *cols, *off, *f177, *f177b;
    float *wb1, *wb2, *wb3, *fw, *adw, *def0, *def1, *s1o, *s2o, *swa, *swb;
    cudaGetSymbolAddress((void**)&xenc,  g_xenc);
    cudaGetSymbolAddress((void**)&yenc,  g_yenc);
    cudaGetSymbolAddress((void**)&f512a, g_f512a);
    cudaGetSymbolAddress((void**)&f512b, g_f512b);
    cudaGetSymbolAddress((void**)&cols,  g_cols);
    cudaGetSymbolAddress((void**)&off,   g_offb);
    cudaGetSymbolAddress((void**)&f177,  g_f177);
    cudaGetSymbolAddress((void**)&f177b, g_f177b);
    cudaGetSymbolAddress((void**)&wb1,   g_wb1);
    cudaGetSymbolAddress((void**)&wb2,   g_wb2);
    cudaGetSymbolAddress((void**)&wb3,   g_wb3);
    cudaGetSymbolAddress((void**)&fw,    g_fwb);
    cudaGetSymbolAddress((void**)&adw,   g_adw);
    cudaGetSymbolAddress((void**)&def0,  g_def0);
    cudaGetSymbolAddress((void**)&def1,  g_def1);
    cudaGetSymbolAddress((void**)&s1o,   g_s1o);
    cudaGetSymbolAddress((void**)&s2o,   g_s2o);
    cudaGetSymbolAddress((void**)&swa,   g_swa);
    cudaGetSymbolAddress((void**)&swb,   g_swb);

    const long long imgStride = 2LL * 256 * HW2;

    auto GEMM = [&](const float* A, const float* Bm, float* C, int M, int N, int K,
                    long long sA, long long sB, long long sC,
                    const float* bias, int relu) {
        dim3 g((N + 63) / 64, (M + 63) / 64, 2);
        gemm64<<<g, dim3(16, 16)>>>(A, Bm, C, M, N, K, sA, sB, sC, bias, relu);
    };
    auto DIM2COL = [&](const float* src, long long sB, const float* offp, int C) {
        dim3 g((HW2 + 255) / 256, 18, (C + 63) / 64);
        deform_im2col_k<<<g, 256>>>(src, sB, offp, cols, C);
    };
    auto IM2COL = [&](const float* src, long long sB, int C, int H, int W,
                      int KH, int KW, int st, int pad, int OH, int OW) {
        dim3 g((OH * OW + 255) / 256, C * KH * KW, 2);
        im2col_g<<<g, 256>>>(src, sB, cols, C, H, W, KH, KW, st, pad, OH, OW);
    };
    auto CONV3D = [&](const float* in, long long inB, const float* w, float* o,
                      long long oB, int C, int O, int relu) {
        dim3 g((HW2 + 255) / 256, O, 2);
        conv3x3_direct<<<g, 256>>>(in, inB, w, o, oB, C, relu);
    };
    auto WBRANCH = [&](const float* feat, const float* wa, const float* wb,
                       const float* wc, int Mc) {
        IM2COL(feat, 177LL * HW2, 177, 48, 48, 5, 5, 2, 2, 24, 24);
        GEMM(wa, cols, wb1, 64, 576, 4425, 0, 4425LL * 576, 64LL * 576, nullptr, 1);
        IM2COL(wb1, 64LL * 576, 64, 24, 24, 5, 5, 2, 2, 12, 12);
        GEMM(wb, cols, wb2, 64, 144, 1600, 0, 1600LL * 144, 64LL * 144, nullptr, 1);
        IM2COL(wb2, 64LL * 144, 64, 12, 12, 3, 3, 2, 1, 6, 6);
        GEMM(wc, cols, wb3, Mc, 36, 576, 0, 576LL * 36, (long long)Mc * 36, nullptr, 0);
        int tot = 2 * Mc;
        mean36_k<<<(tot + 255) / 256, 256>>>(wb3, fw, tot);
    };

    // ---- encoders (1x1 conv == GEMM on NCHW directly) ----
    GEMM(enc0_w, inp,             xenc, 64, HW2, 256, 0, imgStride, 64LL * HW2, enc0_b, 0);
    GEMM(enc1_w, inp + 256 * HW2, yenc, 64, HW2, 256, 0, imgStride, 64LL * HW2, enc1_b, 0);

    auto BRANCH = [&](int br, float* gdef, float* gsw) {
        const float* imgA = (br == 0) ? inp : inp + 256 * HW2;
        const float* imgB = inp + 256 * HW2;   // y for both branches

        // ---- stsn_offset ----
        {
            int tot = 2 * 512 * HW2;
            concat_k<<<(tot + 255) / 256, 256>>>(imgA, imgB, f512a, imgStride);
        }
        float* cur = f512a; float* oth = f512b;
        for (int i = 0; i < 3; i++) {
            CONV3D(cur, 512LL * HW2, offw[i], off, 18LL * HW2, 512, 18, 0);
            DIM2COL(cur, 512LL * HW2, off, 512);
            GEMM(defw[i], cols, oth, 512, HW2, 4608, 0, 4608LL * HW2, 512LL * HW2, nullptr, 0);
            float* t = cur; cur = oth; oth = t;
        }
        CONV3D(cur, 512LL * HW2, offw[3], off, 18LL * HW2, 512, 18, 0);  // final offset -> g_offb

        // ---- astsn_weight ----
        const float* Ra = R0 + (br == 0 ? 0 : 64 * HW2);   // R_pre / R_cur
        const float* Tb = T0 + 64 * HW2;                    // T_cur
        const float* eA = (br == 0) ? xenc : yenc;
        const float* eB = yenc;
        {
            int tot = 2 * 49 * HW2;
            corr_k<<<(tot + 255) / 256, 256>>>(Ra, Tb, f177);
        }
        {
            int tot = 2 * 64 * HW2;
            pack_k<<<(tot + 255) / 256, 256>>>(eA, eB, f177);
        }
        WBRANCH(f177, w0a, w0b, w0c, 177);
        {
            int tot = 2 * 177 * 1593;
            mkw_k<<<(tot + 255) / 256, 256>>>(fw, wx_w, wx_b, adw, 177, 1593, tot);
        }
        DIM2COL(f177, 177LL * HW2, nullptr, 177);
        GEMM(adw, cols, f177b, 177, HW2, 1593, 177LL * 1593, 1593LL * HW2, 177LL * HW2,
             nullptr, 1);
        WBRANCH(f177b, w1a, w1b, w1c, 256);
        {
            int tot = 2 * 256 * 2304;
            mkw_k<<<(tot + 255) / 256, 256>>>(fw, wxf_w, wxf_b, adw, 256, 2304, tot);
        }

        // ---- adaptive deform conv ----
        DIM2COL(imgA, imgStride, off, 256);
        GEMM(adw, cols, gdef, 256, HW2, 2304, 256LL * 2304, 2304LL * HW2, 256LL * HW2,
             nullptr, 0);

        // ---- s_net ----
        DIM2COL(gdef, 256LL * HW2, nullptr, 256);
        GEMM(s1w, cols, s1o, 128, HW2, 2304, 0, 2304LL * HW2, 128LL * HW2, nullptr, 1);
        DIM2COL(s1o, 128LL * HW2, nullptr, 128);
        GEMM(s2w, cols, s2o, 64, HW2, 1152, 0, 1152LL * HW2, 64LL * HW2, nullptr, 1);
        CONV3D(s2o, 64LL * HW2, s3w, gsw, (long long)HW2, 64, 1, 1);
    };

    BRANCH(0, def0, swa);
    BRANCH(1, def1, swb);

    {
        int tot = 2 * 256 * HW2;
        final_k<<<(tot + 255) / 256, 256>>>(def0, def1, swa, swb, out, tot);
    }
}